// round 13
// baseline (speedup 1.0000x reference)
#include <cuda_runtime.h>
#include <cuda_fp16.h>
#include <cstdint>

// ---------------- problem constants ----------------
#define NB     4096
#define NPOL   3849
#define NDROP  7
#define SCALE  0.0625f          // 1/sqrt(256)
#define BST    97               // board staging stride (breaks bank conflicts)

// ---------------- smem layout (bytes), per CTA (1 batch), 96KB ----------------
// RS [0,49152):    X fp16 [96][512B] swz512 (GEMM1 A)
//                  during GEMM2: W-bufs @+0 and @+16384 (X dead)
//                  after GEMM2:  S fp16 [96][512B] swz512 (GEMM3 A)
//                  after GEMM3:  board f32 [96][97] @+0
// RP [49152,98304): PE fp16 [96][512B] swz512 (GEMM1 out, GEMM2 A, GEMM3 B)
//                  during GEMM1: W-bufs @+0 and @+16384 (PE written only at epilogue)
#define RS        0u
#define RP        49152u
#define SMEM_TOT  98304u

// ---------------- device scratch ----------------
__device__ __align__(128) __half g_WE  [256*256];   // We^T  [n][k]
__device__ __align__(128) __half g_W2  [256*256];   // SCALE*(Wq Wk^T)^T  [n][k]
__device__ __align__(128) __half g_SEXT[10*256];    // S_ext rows 81..90
__device__ float g_CONST[16];                        // [0]=cQK [1..7]=cdrop [8]=ckwp
__device__ __align__(16) int2 g_MAP2[NPOL + 1];      // packed gather: offA|offB<<16, offC

// ---------------- helpers ----------------
__device__ __forceinline__ uint32_t swz512(uint32_t o) { return o ^ ((o >> 5) & 0x70); }
// 64B-row weight-chunk swizzle: conflict-free for 8 consecutive rows
__device__ __forceinline__ uint32_t swzB(uint32_t o)   { return o ^ (((o >> 7) & 3) << 4); }

__device__ __forceinline__ uint32_t pack2(float a, float b) {
    __half2 h = __floats2half2_rn(a, b);
    return *reinterpret_cast<uint32_t*>(&h);
}

__device__ __forceinline__ void ldsm4(uint32_t& r0, uint32_t& r1, uint32_t& r2, uint32_t& r3, uint32_t addr) {
    asm volatile("ldmatrix.sync.aligned.m8n8.x4.shared.b16 {%0,%1,%2,%3}, [%4];\n"
                 : "=r"(r0), "=r"(r1), "=r"(r2), "=r"(r3) : "r"(addr));
}

__device__ __forceinline__ void ldsm2(uint32_t& r0, uint32_t& r1, uint32_t addr) {
    asm volatile("ldmatrix.sync.aligned.m8n8.x2.shared.b16 {%0,%1}, [%2];\n"
                 : "=r"(r0), "=r"(r1) : "r"(addr));
}

__device__ __forceinline__ void mma16816(float* c, uint32_t a0, uint32_t a1, uint32_t a2, uint32_t a3,
                                         uint32_t b0, uint32_t b1) {
    asm volatile("mma.sync.aligned.m16n8k16.row.col.f32.f16.f16.f32 "
                 "{%0,%1,%2,%3},{%4,%5,%6,%7},{%8,%9},{%0,%1,%2,%3};\n"
                 : "+f"(c[0]), "+f"(c[1]), "+f"(c[2]), "+f"(c[3])
                 : "r"(a0), "r"(a1), "r"(a2), "r"(a3), "r"(b0), "r"(b1));
}

// mish(x) = x - 2x/(u^2+2u+2), u=e^x
__device__ __forceinline__ float mishf(float v) {
    float u = __expf(v);
    float d = u * u + 2.f * u + 2.f;
    return v - __fdividef(2.f * v, d);
}

__device__ __forceinline__ void cp_async16(uint32_t dst, const void* src) {
    asm volatile("cp.async.cg.shared.global [%0], [%1], 16;\n" :: "r"(dst), "l"(src));
}
__device__ __forceinline__ void cp_commit() { asm volatile("cp.async.commit_group;\n" ::: "memory"); }
template<int N> __device__ __forceinline__ void cp_wait() {
    asm volatile("cp.async.wait_group %0;\n" :: "n"(N) : "memory");
}

// ---------------- unified prep kernel ----------------
__global__ void prep_all(const float* __restrict__ We, const float* __restrict__ Wq,
                         const float* __restrict__ Wk, const float* __restrict__ Wp,
                         const float* __restrict__ bq, const float* __restrict__ bk,
                         const float* __restrict__ bp, const float* __restrict__ dqm,
                         const void* __restrict__ rawp, const void* __restrict__ polp) {
    __shared__ float wkrow[256];
    int bid = blockIdx.x, tid = threadIdx.x;
    int lane = tid & 31, w = tid >> 5;

    if (bid < 256) {
        int n = bid, k = tid;
        g_WE[n*256 + k] = __float2half(We[k*256 + n]);
        wkrow[k] = Wk[n*256 + k];
        __syncthreads();
        const float4* wq = (const float4*)(Wq + (size_t)k * 256);
        float s = 0.f;
        #pragma unroll 8
        for (int o = 0; o < 64; ++o) {
            float4 q = wq[o];
            s += q.x * wkrow[4*o] + q.y * wkrow[4*o+1] + q.z * wkrow[4*o+2] + q.w * wkrow[4*o+3];
        }
        g_W2[n*256 + k] = __float2half(s * SCALE);
    } else if (bid < 512) {
        int j = bid - 256;
        #pragma unroll
        for (int pass = 0; pass < 2; ++pass) {
            int t = (pass == 0) ? w : ((w < 2) ? 8 + w : -1);
            if (t < 0) continue;
            float s = 0.f;
            for (int o = lane; o < 256; o += 32) {
                float term;
                if (t < 7)       term = dqm[t*256 + o] * Wk[j*256 + o];
                else if (t == 7) term = Wk[j*256 + o] * Wp[o];
                else if (t == 8) term = Wk[j*256 + o] * bq[o];
                else             term = Wq[j*256 + o] * bk[o];
                s += term;
            }
            #pragma unroll
            for (int off = 16; off; off >>= 1) s += __shfl_xor_sync(0xffffffffu, s, off);
            if (lane == 0) g_SEXT[t*256 + j] = __float2half((t == 7) ? s : s * SCALE);
        }
    } else if (bid == 512) {
        #pragma unroll
        for (int pass = 0; pass < 2; ++pass) {
            float s = 0.f;
            int which = -1;
            if (pass == 0) {
                if (w == 0) { for (int o = lane; o < 256; o += 32) s += bq[o] * bk[o]; which = 0; }
                else        { for (int o = lane; o < 256; o += 32) s += dqm[(w-1)*256 + o] * bk[o]; which = w; }
            } else if (w == 0) {
                for (int o = lane; o < 256; o += 32) s += bk[o] * Wp[o];
                which = 8;
            }
            if (which < 0) continue;
            #pragma unroll
            for (int off = 16; off; off >>= 1) s += __shfl_xor_sync(0xffffffffu, s, off);
            if (lane == 0) g_CONST[which] = (which == 8) ? (s + bp[0]) : (s * SCALE);
        }
        if (tid == 0) g_MAP2[NPOL] = make_int2(92 * BST, 92 * BST);   // pad slot -> zero cell
    } else {
        int j = (bid - 513) * 256 + tid;
        if (j < NPOL) {
            const int* r32 = (const int*)rawp;
            bool is64 = (r32[1] == 0 && r32[3] == 0 && r32[5] == 0 && r32[7] == 0);
            long long rv, pv;
            if (is64) { rv = ((const long long*)rawp)[j]; pv = ((const long long*)polp)[j]; }
            else      { rv = r32[j];                      pv = ((const int*)polp)[j]; }
            int r = (int)rv;
            int offA, offB, offC;
            if (r < 13122) {
                int rr = (r < 6561) ? r : r - 6561;
                int q = rr / 81, k = rr - q * 81;
                offA = q * BST + k;
                offB = 90 * BST + q;
                offC = (r < 6561) ? (89 * BST + k) : (91 * BST + k);
            } else {
                int r3 = r - 13122;
                int n = r3 / 81, k = r3 - n * 81;
                offA = (81 + n) * BST + k;
                offB = 92 * BST;
                offC = 92 * BST;
            }
            g_MAP2[(int)pv] = make_int2(offA | (offB << 16), offC);
        }
    }
}

// ---------------- fused-kernel building blocks ----------------
// prefetch one [256n][32k] 16KB chunk (k-chunk kc) into buffer at dst
__device__ __forceinline__ void pfW(uint32_t dst, const __half* __restrict__ W,
                                    int kc, int tid) {
    #pragma unroll
    for (int t = 0; t < 4; ++t) {
        int i = tid + t * 256;                 // 1024 sites: 256 rows x 4 x 16B
        int r = i >> 2, s = i & 3;
        cp_async16(dst + swzB((uint32_t)(r * 64 + s * 16)),
                   W + (size_t)r * 256 + kc * 32 + s * 8);
    }
    cp_commit();
}

// one [96m x 64n-per-warp x 32k] sub-GEMM; A at aOff (512B rows swz512), full n=256.
__device__ __forceinline__ void mma_g(float acc[3][8][4], uint32_t sbase, uint32_t aOff,
                                      int kc, uint32_t bOff, int lane, int wm, int wn) {
    uint32_t aBase[3], bBase[4];
    #pragma unroll
    for (int i = 0; i < 3; ++i) {
        int row = wm*48 + i*16 + (lane & 15);
        aBase[i] = sbase + aOff + swz512((uint32_t)(row*512 + kc*64 + ((lane >> 4) << 4)));
    }
    #pragma unroll
    for (int jj = 0; jj < 4; ++jj) {
        int nrow = wn*64 + jj*16 + (lane & 7) + ((lane >> 4) << 3);
        bBase[jj] = sbase + bOff + swzB((uint32_t)(nrow*64 + (((lane >> 3) & 1) << 4)));
    }
    #pragma unroll
    for (int ks = 0; ks < 2; ++ks) {
        uint32_t kx = (uint32_t)(ks << 5);
        uint32_t a[3][4];
        #pragma unroll
        for (int i = 0; i < 3; ++i)
            ldsm4(a[i][0], a[i][1], a[i][2], a[i][3], aBase[i] ^ kx);
        #pragma unroll
        for (int jj = 0; jj < 4; ++jj) {
            uint32_t b0, b1, b2, b3;
            ldsm4(b0, b1, b2, b3, bBase[jj] ^ kx);
            #pragma unroll
            for (int i = 0; i < 3; ++i) {
                mma16816(acc[i][jj*2],   a[i][0], a[i][1], a[i][2], a[i][3], b0, b1);
                mma16816(acc[i][jj*2+1], a[i][0], a[i][1], a[i][2], a[i][3], b2, b3);
            }
        }
    }
}

// GEMM3 partial for k-tile jg: board += S[:, jg*64..][96x64] * PE[:, jg*64..]^T
__device__ __forceinline__ void gemm3_part(float acc3[3][3][4], uint32_t sbase, int jg,
                                           int lane, int wm, int wn) {
    uint32_t aBase[3];
    #pragma unroll
    for (int i = 0; i < 3; ++i) {
        int row = wm*48 + i*16 + (lane & 15);
        aBase[i] = sbase + RS + swz512((uint32_t)(row*512 + jg*128 + ((lane >> 4) << 4)));
    }
    uint32_t n0 = (uint32_t)(wn * 24);
    uint32_t b4Base = sbase + RP + swz512((n0 + (lane & 7) + ((lane >> 4) << 3)) * 512
                                          + (uint32_t)(jg*128) + (((lane >> 3) & 1) << 4));
    uint32_t b2Base = sbase + RP + swz512((n0 + 16 + (lane & 7)) * 512
                                          + (uint32_t)(jg*128) + (((lane >> 3) & 1) << 4));
    #pragma unroll
    for (int ks = 0; ks < 4; ++ks) {
        uint32_t kx = (uint32_t)(ks << 5);
        uint32_t a[3][4];
        #pragma unroll
        for (int i = 0; i < 3; ++i)
            ldsm4(a[i][0], a[i][1], a[i][2], a[i][3], aBase[i] ^ kx);
        uint32_t b0, b1, b2, b3, b4, b5;
        ldsm4(b0, b1, b2, b3, b4Base ^ kx);
        ldsm2(b4, b5, b2Base ^ kx);
        #pragma unroll
        for (int i = 0; i < 3; ++i) {
            mma16816(acc3[i][0], a[i][0], a[i][1], a[i][2], a[i][3], b0, b1);
            mma16816(acc3[i][1], a[i][0], a[i][1], a[i][2], a[i][3], b2, b3);
            mma16816(acc3[i][2], a[i][0], a[i][1], a[i][2], a[i][3], b4, b5);
        }
    }
}

// ---------------- fused kernel: one CTA per batch, 2 CTAs/SM ----------------
__global__ void __launch_bounds__(256, 2) k_fused(const float* __restrict__ X,
                                                  const float* __restrict__ be,
                                                  float* __restrict__ out) {
    extern __shared__ char sm[];
    uint32_t sbase = (uint32_t)__cvta_generic_to_shared(sm);
    int tid = threadIdx.x, lane = tid & 31, w = tid >> 5;
    int wm = w >> 2, wn = w & 3;              // 2m x 4n grid
    int rl = lane >> 2, cl = (lane & 3) * 2;
    int b = blockIdx.x;

    // ---- GEMM1 chunk0 in flight (buf in PE region); X -> fp16 swz512 @RS ----
    pfW(sbase + RP, g_WE, 0, tid);
    for (int idx = tid; idx < 3072; idx += 256) {
        int r = idx >> 5, c = idx & 31;
        uint4 u = make_uint4(0u, 0u, 0u, 0u);
        if (r < 81) {
            const float4* p = (const float4*)(X + ((size_t)b * 81 + r) * 256 + c * 8);
            float4 f0 = p[0], f1 = p[1];
            u.x = pack2(f0.x, f0.y); u.y = pack2(f0.z, f0.w);
            u.z = pack2(f1.x, f1.y); u.w = pack2(f1.z, f1.w);
        }
        *(uint4*)(sm + RS + swz512((uint32_t)(r * 512 + c * 16))) = u;
    }

    // ---- GEMM1: PE = mish(X @ We^T + be), single n=256 pass, 8 k-chunks of 32 ----
    {
        float acc[3][8][4] = {};
        for (int c = 0; c < 8; ++c) {
            cp_wait<0>();
            __syncthreads();
            if (c < 7) pfW(sbase + RP + (uint32_t)(((c + 1) & 1) ? 16384u : 0u), g_WE, c + 1, tid);
            mma_g(acc, sbase, RS, c, RP + (uint32_t)((c & 1) ? 16384u : 0u), lane, wm, wn);
        }
        __syncthreads();                       // X + W-buf reads done
        pfW(sbase + RS, g_W2, 0, tid);         // GEMM2 chunk0 into dead X region
        // PE epilogue (overwrites W-buf area; bias via __ldg, cached)
        #pragma unroll
        for (int i = 0; i < 3; ++i) {
            int r = wm*48 + i*16 + rl;
            #pragma unroll
            for (int j8 = 0; j8 < 8; ++j8) {
                int col = wn*64 + j8*8 + cl;
                float b0 = __ldg(be + col), b1 = __ldg(be + col + 1);
                uint32_t w0 = 0u, w1 = 0u;
                if (r < 81)
                    w0 = pack2(mishf(acc[i][j8][0] + b0), mishf(acc[i][j8][1] + b1));
                if (r + 8 < 81)
                    w1 = pack2(mishf(acc[i][j8][2] + b0), mishf(acc[i][j8][3] + b1));
                *(uint32_t*)(sm + RP + swz512((uint32_t)(r * 512 + col * 2))) = w0;
                *(uint32_t*)(sm + RP + swz512((uint32_t)((r + 8) * 512 + col * 2))) = w1;
            }
        }
    }

    // ---- GEMM2: S = PE @ W2, single n=256 pass (W-bufs in dead X region) ----
    {
        float acc[3][8][4] = {};
        for (int c = 0; c < 8; ++c) {
            cp_wait<0>();
            __syncthreads();
            if (c < 7) pfW(sbase + RS + (uint32_t)(((c + 1) & 1) ? 16384u : 0u), g_W2, c + 1, tid);
            mma_g(acc, sbase, RP, c, RS + (uint32_t)((c & 1) ? 16384u : 0u), lane, wm, wn);
        }
        __syncthreads();                       // W-buf reads done -> RS free for S
        // S epilogue: fp16 [96][512B] swz512 @RS; rows 81-95 from SEXT/zero
        #pragma unroll
        for (int i = 0; i < 3; ++i) {
            int r = wm*48 + i*16 + rl;
            #pragma unroll
            for (int j8 = 0; j8 < 8; ++j8) {
                int col = wn*64 + j8*8 + cl;
                if (r < 81)
                    *(uint32_t*)(sm + RS + swz512((uint32_t)(r * 512 + col * 2))) =
                        pack2(acc[i][j8][0], acc[i][j8][1]);
                if (r + 8 < 81)
                    *(uint32_t*)(sm + RS + swz512((uint32_t)((r + 8) * 512 + col * 2))) =
                        pack2(acc[i][j8][2], acc[i][j8][3]);
            }
        }
        for (int idx = tid; idx < 480; idx += 256) {   // rows 81-95 x 32 x 16B
            int t = idx >> 5, cc = idx & 31;
            uint4 v = make_uint4(0u, 0u, 0u, 0u);
            if (t < 10) v = *(const uint4*)&g_SEXT[t * 256 + cc * 8];
            *(uint4*)(sm + RS + swz512((uint32_t)((81 + t) * 512 + cc * 16))) = v;
        }
    }
    __syncthreads();

    // ---- GEMM3: board = S @ PE^T (96x96x256) ----
    float acc3[3][3][4] = {};
    gemm3_part(acc3, sbase, 0, lane, wm, wn);
    gemm3_part(acc3, sbase, 1, lane, wm, wn);
    gemm3_part(acc3, sbase, 2, lane, wm, wn);
    gemm3_part(acc3, sbase, 3, lane, wm, wn);
    __syncthreads();                           // S/PE reads done -> RS free for board

    // ---- board staging: f32 [96][BST] @RS ----
    {
        float* stag = (float*)(sm + RS);
        #pragma unroll
        for (int i = 0; i < 3; ++i) {
            int r = wm*48 + i*16 + rl;
            #pragma unroll
            for (int jb = 0; jb < 3; ++jb) {
                int col = wn*24 + jb*8 + cl;
                stag[r * BST + col]           = acc3[i][jb][0];
                stag[r * BST + col + 1]       = acc3[i][jb][1];
                stag[(r + 8) * BST + col]     = acc3[i][jb][2];
                stag[(r + 8) * BST + col + 1] = acc3[i][jb][3];
            }
        }
    }
    __syncthreads();

    // ---- fixups: fold constants into aux rows ----
    {
        float* bs = (float*)(sm + RS);
        float cQK  = g_CONST[0];
        float ckwp = g_CONST[8];
        for (int t = tid; t < 729; t += 256) {
            if (t < 81)       bs[90 * BST + t] += cQK;
            else if (t < 162) { int k = t - 81; bs[91 * BST + k] = bs[89 * BST + k] + bs[88 * BST + k] + ckwp; }
            else              { int u2 = t - 162; int n = u2 / 81, k = u2 - n * 81;
                                bs[(81 + n) * BST + k] += g_CONST[1 + n]; }
        }
    }
    __syncthreads();

    // ---- permuted gather: 2 policies per thread via int4 map loads ----
    {
        const float* bs = (const float*)(sm + RS);
        float* ob = out + (size_t)b * NPOL;
        for (int p = tid * 2; p < NPOL; p += 512) {
            int4 m = *(const int4*)&g_MAP2[p];
            float v0 = bs[m.x & 0xffff] + bs[m.x >> 16] + bs[m.y];
            float v1 = bs[m.z & 0xffff] + bs[m.z >> 16] + bs[m.w];
            ob[p] = v0;
            if (p + 1 < NPOL) ob[p + 1] = v1;
        }
    }
}

// ---------------- launch ----------------
extern "C" void kernel_launch(void* const* d_in, const int* in_sizes, int n_in,
                              void* d_out, int out_size) {
    const float* x   = (const float*)d_in[0];
    const float* We  = (const float*)d_in[1];
    const float* be  = (const float*)d_in[2];
    const float* Wq  = (const float*)d_in[3];
    const float* bq  = (const float*)d_in[4];
    const float* Wk  = (const float*)d_in[5];
    const float* bk  = (const float*)d_in[6];
    const float* Wp  = (const float*)d_in[7];
    const float* bp  = (const float*)d_in[8];
    const float* dq  = (const float*)d_in[9];
    const void*  raw = d_in[10];
    const void*  pol = d_in[11];
    float* out = (float*)d_out;

    cudaFuncSetAttribute(k_fused, cudaFuncAttributeMaxDynamicSharedMemorySize, SMEM_TOT);

    prep_all<<<529, 256>>>(We, Wq, Wk, Wp, bq, bk, bp, dq, raw, pol);
    k_fused<<<NB, 256, SMEM_TOT>>>(x, be, out);
}